// round 3
// baseline (speedup 1.0000x reference)
#include <cuda_runtime.h>
#include <cuda_bf16.h>
#include <cstdint>

// Problem constants
#define NN  50000
#define EE  1600000
#define DD  128
#define RR  8
#define K1  1024         // R*D
#define KTOT 1152        // R*D + D
#define NR  (NN*RR)      // 400000
#define LN_EPS 1e-5f

// Scratch (device globals — allocation is forbidden)
__device__ float g_hbuf[(size_t)NN * K1];   // 204.8 MB: normalized per-(node,rel) sums
__device__ int   g_cnt[NR];
__device__ int   g_off[NR];
__device__ int   g_cur[NR];
__device__ int   g_src[EE];                 // src id per edge (int32-normalized)
__device__ int   g_key[EE];                 // dst*R+rel per edge
__device__ int   g_srt[EE];                 // src ids, bucket-sorted
__device__ int   g_total;
__device__ int   g_ei64, g_et64;            // dtype flags for index inputs

// ---------------------------------------------------------------------------
// Detect whether edge_index / edge_type arrive as int64 or int32.
// For int64 values < 2^31 (node ids, rel ids), every odd 32-bit word is 0.
// For int32 data those words are random ids — OR over 2048+ words decides.
// ---------------------------------------------------------------------------
__global__ void k_detect(const unsigned int* __restrict__ ei_w,
                         const unsigned int* __restrict__ et_w) {
    __shared__ unsigned int a_ei, a_et;
    if (threadIdx.x == 0) { a_ei = 0u; a_et = 0u; }
    __syncthreads();
    unsigned int vei = 0u, vet = 0u;
#pragma unroll
    for (int j = 0; j < 8; j++) {
        int idx = threadIdx.x * 8 + j;          // 0..2047
        vei |= ei_w[2 * idx + 1];
        vet |= et_w[2 * idx + 1];
    }
    atomicOr(&a_ei, vei);
    atomicOr(&a_et, vet);
    __syncthreads();
    if (threadIdx.x == 0) {
        g_ei64 = (a_ei == 0u) ? 1 : 0;
        g_et64 = (a_et == 0u) ? 1 : 0;
    }
}

__global__ void k_zero_cnt() {
    int i = blockIdx.x * blockDim.x + threadIdx.x;
    if (i < NR) g_cnt[i] = 0;
    if (i == 0) g_total = 0;
}

// Normalize indices to int32, build keys, count bucket sizes.
__global__ void k_prep(const void* __restrict__ ei_v,
                       const void* __restrict__ et_v) {
    int e = blockIdx.x * blockDim.x + threadIdx.x;
    if (e >= EE) return;
    int s, d, r;
    if (g_ei64) {
        const long long* p = (const long long*)ei_v;
        s = (int)p[e];
        d = (int)p[EE + e];
    } else {
        const int* p = (const int*)ei_v;
        s = p[e];
        d = p[EE + e];
    }
    if (g_et64) r = (int)((const long long*)et_v)[e];
    else        r = ((const int*)et_v)[e];
    int key = d * RR + r;
    g_src[e] = s;
    g_key[e] = key;
    atomicAdd(&g_cnt[key], 1);
}

// Disjoint bucket ranges via warp-aggregated atomic bump.
__global__ void k_offsets() {
    int i = blockIdx.x * blockDim.x + threadIdx.x;
    int lane = threadIdx.x & 31;
    int val = (i < NR) ? g_cnt[i] : 0;
    int incl = val;
#pragma unroll
    for (int o = 1; o < 32; o <<= 1) {
        int n = __shfl_up_sync(0xffffffffu, incl, o);
        if (lane >= o) incl += n;
    }
    int excl = incl - val;
    int wtot = __shfl_sync(0xffffffffu, incl, 31);
    int base = 0;
    if (lane == 0) base = atomicAdd(&g_total, wtot);
    base = __shfl_sync(0xffffffffu, base, 0);
    if (i < NR) {
        g_off[i] = base + excl;
        g_cur[i] = base + excl;
    }
}

// Scatter edge src ids into their (dst,rel) bucket.
__global__ void k_bucket() {
    int e = blockIdx.x * blockDim.x + threadIdx.x;
    if (e < EE) {
        int pos = atomicAdd(&g_cur[g_key[e]], 1);
        g_srt[pos] = g_src[e];
    }
}

// One warp per bucket: hbuf[b,:] = (1/max(cnt,1)) * sum_{e in b} x[src_e,:]
__global__ __launch_bounds__(256)
void k_gather(const float* __restrict__ x) {
    int w = (blockIdx.x * blockDim.x + threadIdx.x) >> 5;
    if (w >= NR) return;
    int lane = threadIdx.x & 31;
    int start = g_off[w];
    int n = g_cnt[w];
    float4 acc = make_float4(0.f, 0.f, 0.f, 0.f);
    int j = 0;
    for (; j + 1 < n; j += 2) {
        int s0 = g_srt[start + j];
        int s1 = g_srt[start + j + 1];
        float4 v0 = *(const float4*)(x + (size_t)s0 * DD + lane * 4);
        float4 v1 = *(const float4*)(x + (size_t)s1 * DD + lane * 4);
        acc.x += v0.x + v1.x; acc.y += v0.y + v1.y;
        acc.z += v0.z + v1.z; acc.w += v0.w + v1.w;
    }
    if (j < n) {
        int s0 = g_srt[start + j];
        float4 v0 = *(const float4*)(x + (size_t)s0 * DD + lane * 4);
        acc.x += v0.x; acc.y += v0.y; acc.z += v0.z; acc.w += v0.w;
    }
    float sc = 1.0f / fmaxf((float)n, 1.0f);
    acc.x *= sc; acc.y *= sc; acc.z *= sc; acc.w *= sc;
    *(float4*)(g_hbuf + (size_t)w * DD + lane * 4) = acc;
}

// ---------------------------------------------------------------------------
// Fused GEMM + bias + LayerNorm + ReLU. BM=64, BN=128, BK=32, 256 threads.
// ---------------------------------------------------------------------------
__global__ __launch_bounds__(256)
void k_gemm_ln(const float* __restrict__ x,
               const float* __restrict__ Wrel,   // [1024,128]
               const float* __restrict__ Wroot,  // [128,128]
               const float* __restrict__ bias,
               const float* __restrict__ gamma,
               const float* __restrict__ beta,
               float* __restrict__ out) {
    __shared__ float smem[64 * 132];
    float* As = smem;            // [32][64] k-major
    float* Bs = smem + 2048;     // [32][128]

    const int t  = threadIdx.x;
    const int ty = t >> 4;
    const int tx = t & 15;
    const int rowBase = blockIdx.x * 64;

    float c[4][8];
#pragma unroll
    for (int i = 0; i < 4; i++)
#pragma unroll
        for (int j = 0; j < 8; j++) c[i][j] = 0.f;

    for (int k0 = 0; k0 < KTOT; k0 += 32) {
#pragma unroll
        for (int i = 0; i < 2; i++) {
            int q  = t + 256 * i;
            int m  = q >> 3;
            int kq = (q & 7) * 4;
            int gRow = rowBase + m;
            float4 a = make_float4(0.f, 0.f, 0.f, 0.f);
            int kk = k0 + kq;
            if (gRow < NN) {
                if (kk < K1)
                    a = *(const float4*)(g_hbuf + (size_t)gRow * K1 + kk);
                else
                    a = *(const float4*)(x + (size_t)gRow * DD + (kk - K1));
            }
            As[(kq + 0) * 64 + m] = a.x;
            As[(kq + 1) * 64 + m] = a.y;
            As[(kq + 2) * 64 + m] = a.z;
            As[(kq + 3) * 64 + m] = a.w;
        }
#pragma unroll
        for (int i = 0; i < 4; i++) {
            int q  = t + 256 * i;
            int kb = q >> 5;
            int nq = (q & 31) * 4;
            int kk = k0 + kb;
            const float* src = (kk < K1) ? (Wrel + (size_t)kk * DD + nq)
                                         : (Wroot + (size_t)(kk - K1) * DD + nq);
            *(float4*)(Bs + kb * 128 + nq) = *(const float4*)src;
        }
        __syncthreads();

#pragma unroll
        for (int kk = 0; kk < 32; kk++) {
            float4 a4 = *(float4*)(As + kk * 64 + ty * 4);
            float4 b0 = *(float4*)(Bs + kk * 128 + tx * 8);
            float4 b1 = *(float4*)(Bs + kk * 128 + tx * 8 + 4);
            float a[4] = {a4.x, a4.y, a4.z, a4.w};
            float b[8] = {b0.x, b0.y, b0.z, b0.w, b1.x, b1.y, b1.z, b1.w};
#pragma unroll
            for (int i = 0; i < 4; i++)
#pragma unroll
                for (int j = 0; j < 8; j++) c[i][j] = fmaf(a[i], b[j], c[i][j]);
        }
        __syncthreads();
    }

    // epilogue: stage tile (+bias) to smem, then per-row LN + ReLU
    float4 bia0 = *(const float4*)(bias + tx * 8);
    float4 bia1 = *(const float4*)(bias + tx * 8 + 4);
#pragma unroll
    for (int i = 0; i < 4; i++) {
        int m = ty * 4 + i;
        *(float4*)(smem + m * 132 + tx * 8) =
            make_float4(c[i][0] + bia0.x, c[i][1] + bia0.y,
                        c[i][2] + bia0.z, c[i][3] + bia0.w);
        *(float4*)(smem + m * 132 + tx * 8 + 4) =
            make_float4(c[i][4] + bia1.x, c[i][5] + bia1.y,
                        c[i][6] + bia1.z, c[i][7] + bia1.w);
    }
    __syncthreads();

    const int wid  = t >> 5;
    const int lane = t & 31;
    float4 g4  = *(const float4*)(gamma + lane * 4);
    float4 be4 = *(const float4*)(beta + lane * 4);
#pragma unroll
    for (int rr = 0; rr < 8; rr++) {
        int m = wid * 8 + rr;
        int gRow = rowBase + m;
        if (gRow >= NN) continue;
        float4 v = *(float4*)(smem + m * 132 + lane * 4);
        float s  = v.x + v.y + v.z + v.w;
        float ss = v.x * v.x + v.y * v.y + v.z * v.z + v.w * v.w;
#pragma unroll
        for (int o = 16; o > 0; o >>= 1) {
            s  += __shfl_xor_sync(0xffffffffu, s, o);
            ss += __shfl_xor_sync(0xffffffffu, ss, o);
        }
        float mean = s * (1.0f / DD);
        float var  = ss * (1.0f / DD) - mean * mean;
        float rstd = rsqrtf(var + LN_EPS);
        float4 o4;
        o4.x = fmaxf((v.x - mean) * rstd * g4.x + be4.x, 0.f);
        o4.y = fmaxf((v.y - mean) * rstd * g4.y + be4.y, 0.f);
        o4.z = fmaxf((v.z - mean) * rstd * g4.z + be4.z, 0.f);
        o4.w = fmaxf((v.w - mean) * rstd * g4.w + be4.w, 0.f);
        ((float4*)out)[(size_t)gRow * 32 + lane] = o4;
    }
}

// ---------------------------------------------------------------------------
extern "C" void kernel_launch(void* const* d_in, const int* in_sizes, int n_in,
                              void* d_out, int out_size) {
    const float* x  = (const float*)d_in[0];
    const void*  ei = d_in[1];
    const void*  et = d_in[2];
    int base = 3;
    if (n_in > 3 && in_sizes[3] == 1) base = 4;   // skip scalar node_num if present
    const float* Wrel  = (const float*)d_in[base + 0];
    const float* Wroot = (const float*)d_in[base + 1];
    const float* bias  = (const float*)d_in[base + 2];
    const float* gamma = (const float*)d_in[base + 3];
    const float* beta  = (const float*)d_in[base + 4];
    float* out = (float*)d_out;

    k_detect <<<1, 256>>>((const unsigned int*)ei, (const unsigned int*)et);
    k_zero_cnt<<<(NR + 255) / 256, 256>>>();
    k_prep   <<<(EE + 255) / 256, 256>>>(ei, et);
    k_offsets<<<(NR + 255) / 256, 256>>>();
    k_bucket <<<(EE + 255) / 256, 256>>>();
    k_gather <<<(NR * 32 + 255) / 256, 256>>>(x);
    k_gemm_ln<<<(NN + 63) / 64, 256>>>(x, Wrel, Wroot, bias, gamma, beta, out);
}

// round 5
// speedup vs baseline: 2.9095x; 2.9095x over previous
#include <cuda_runtime.h>
#include <cuda_bf16.h>
#include <cstdint>

// Problem constants
#define NN  50000
#define EE  1600000
#define DD  128
#define RR  8
#define NR  (NN*RR)      // 400000
#define KT  1152         // R*D + D
#define NPAD 50048       // 391 * 128
#define LN_EPS 1e-5f
#define NCH 72           // KT / 16

// Scratch (device globals — allocation is forbidden). .bss zero-init.
__device__ __align__(256) float g_a[(size_t)NPAD * KT];   // 230.6 MB: [node, 1152] tf32
__device__ __align__(256) float g_wt[128 * KT];           // weights^T [N=128, K=1152]
__device__ int g_cnt[NR], g_off[NR], g_cur[NR];
__device__ int g_src[EE], g_key[EE], g_srt[EE];
__device__ int g_total, g_ei64, g_et64;

// ---------------------------------------------------------------------------
static __device__ __forceinline__ float to_tf32(float f) {
    float r; asm("cvt.rna.tf32.f32 %0, %1;" : "=f"(r) : "f"(f)); return r;
}
static __device__ __forceinline__ uint32_t smem_u32(const void* p) {
    uint32_t a;
    asm("{ .reg .u64 t; cvta.to.shared.u64 t, %1; cvt.u32.u64 %0, t; }"
        : "=r"(a) : "l"(p));
    return a;
}
static __device__ __forceinline__ void cp16(uint32_t dst, const void* src) {
    asm volatile("cp.async.cg.shared.global [%0], [%1], 16;"
                 :: "r"(dst), "l"(src) : "memory");
}
static __device__ __forceinline__ void mma_tf32(float c[4], const uint32_t a[4],
                                                const uint32_t b[2]) {
    asm volatile(
        "mma.sync.aligned.m16n8k8.row.col.f32.tf32.tf32.f32 "
        "{%0,%1,%2,%3}, {%4,%5,%6,%7}, {%8,%9}, {%0,%1,%2,%3};"
        : "+f"(c[0]), "+f"(c[1]), "+f"(c[2]), "+f"(c[3])
        : "r"(a[0]), "r"(a[1]), "r"(a[2]), "r"(a[3]), "r"(b[0]), "r"(b[1]));
}

// ---------------------------------------------------------------------------
// dtype detection for index inputs (int64 vs int32)
// ---------------------------------------------------------------------------
__global__ void k_detect(const unsigned int* __restrict__ ei_w,
                         const unsigned int* __restrict__ et_w) {
    __shared__ unsigned int a_ei, a_et;
    if (threadIdx.x == 0) { a_ei = 0u; a_et = 0u; }
    __syncthreads();
    unsigned int vei = 0u, vet = 0u;
#pragma unroll
    for (int j = 0; j < 8; j++) {
        int idx = threadIdx.x * 8 + j;
        vei |= ei_w[2 * idx + 1];
        vet |= et_w[2 * idx + 1];
    }
    atomicOr(&a_ei, vei);
    atomicOr(&a_et, vet);
    __syncthreads();
    if (threadIdx.x == 0) {
        g_ei64 = (a_ei == 0u) ? 1 : 0;
        g_et64 = (a_et == 0u) ? 1 : 0;
    }
}

__global__ void k_zero_cnt() {
    int i = blockIdx.x * blockDim.x + threadIdx.x;
    if (i < NR) g_cnt[i] = 0;
    if (i == 0) g_total = 0;
}

__global__ void k_prep(const void* __restrict__ ei_v,
                       const void* __restrict__ et_v) {
    int e = blockIdx.x * blockDim.x + threadIdx.x;
    if (e >= EE) return;
    int s, d, r;
    if (g_ei64) {
        const long long* p = (const long long*)ei_v;
        s = (int)p[e];
        d = (int)p[EE + e];
    } else {
        const int* p = (const int*)ei_v;
        s = p[e];
        d = p[EE + e];
    }
    if (g_et64) r = (int)((const long long*)et_v)[e];
    else        r = ((const int*)et_v)[e];
    int key = d * RR + r;
    g_src[e] = s;
    g_key[e] = key;
    atomicAdd(&g_cnt[key], 1);
}

__global__ void k_offsets() {
    int i = blockIdx.x * blockDim.x + threadIdx.x;
    int lane = threadIdx.x & 31;
    int val = (i < NR) ? g_cnt[i] : 0;
    int incl = val;
#pragma unroll
    for (int o = 1; o < 32; o <<= 1) {
        int n = __shfl_up_sync(0xffffffffu, incl, o);
        if (lane >= o) incl += n;
    }
    int excl = incl - val;
    int wtot = __shfl_sync(0xffffffffu, incl, 31);
    int base = 0;
    if (lane == 0) base = atomicAdd(&g_total, wtot);
    base = __shfl_sync(0xffffffffu, base, 0);
    if (i < NR) {
        g_off[i] = base + excl;
        g_cur[i] = base + excl;
    }
}

__global__ void k_bucket() {
    int e = blockIdx.x * blockDim.x + threadIdx.x;
    if (e < EE) {
        int pos = atomicAdd(&g_cur[g_key[e]], 1);
        g_srt[pos] = g_src[e];
    }
}

// One warp per (dst,rel) bucket: g_a[node, rel*128..] = tf32(mean of x[src])
__global__ __launch_bounds__(256)
void k_gather(const float* __restrict__ x) {
    int w = (blockIdx.x * blockDim.x + threadIdx.x) >> 5;
    if (w >= NR) return;
    int lane = threadIdx.x & 31;
    int start = g_off[w];
    int n = g_cnt[w];
    float4 acc = make_float4(0.f, 0.f, 0.f, 0.f);
    int j = 0;
    for (; j + 1 < n; j += 2) {
        int s0 = g_srt[start + j];
        int s1 = g_srt[start + j + 1];
        float4 v0 = *(const float4*)(x + (size_t)s0 * DD + lane * 4);
        float4 v1 = *(const float4*)(x + (size_t)s1 * DD + lane * 4);
        acc.x += v0.x + v1.x; acc.y += v0.y + v1.y;
        acc.z += v0.z + v1.z; acc.w += v0.w + v1.w;
    }
    if (j < n) {
        int s0 = g_srt[start + j];
        float4 v0 = *(const float4*)(x + (size_t)s0 * DD + lane * 4);
        acc.x += v0.x; acc.y += v0.y; acc.z += v0.z; acc.w += v0.w;
    }
    float sc = 1.0f / fmaxf((float)n, 1.0f);
    int node = w >> 3, rel = w & 7;
    float4 o;
    o.x = to_tf32(acc.x * sc); o.y = to_tf32(acc.y * sc);
    o.z = to_tf32(acc.z * sc); o.w = to_tf32(acc.w * sc);
    *(float4*)(g_a + (size_t)node * KT + rel * 128 + lane * 4) = o;
}

__global__ void k_xcopy(const float* __restrict__ x) {
    int i = blockIdx.x * blockDim.x + threadIdx.x;
    if (i >= NN * 32) return;
    int node = i >> 5, c = (i & 31) * 4;
    float4 v = *(const float4*)(x + (size_t)node * DD + c);
    float4 o;
    o.x = to_tf32(v.x); o.y = to_tf32(v.y);
    o.z = to_tf32(v.z); o.w = to_tf32(v.w);
    *(float4*)(g_a + (size_t)node * KT + 1024 + c) = o;
}

__global__ void k_wprep(const float* __restrict__ Wrel,
                        const float* __restrict__ Wroot) {
    int i = blockIdx.x * blockDim.x + threadIdx.x;
    if (i >= 128 * KT) return;
    int n = i & 127, k = i >> 7;
    float v = (k < 1024) ? Wrel[(size_t)k * 128 + n]
                         : Wroot[(size_t)(k - 1024) * 128 + n];
    g_wt[(size_t)n * KT + k] = to_tf32(v);
}

// ---------------------------------------------------------------------------
// tf32 mma.sync GEMM (M=128/CTA, N=128, K=1152) + bias + LN + ReLU.
// 8 warps in 4x2; warp tile 32x64 via m16n8k8. cp.async double buffer, BK=16.
// Smem tiles [row][20] (pad 4) -> conflict-free frag LDS.
// ---------------------------------------------------------------------------
__global__ void __launch_bounds__(256, 2)
k_mma_ln(const float* __restrict__ bias, const float* __restrict__ gamma,
         const float* __restrict__ beta, float* __restrict__ out) {
    __shared__ float sA[2][128 * 20];
    __shared__ float sB[2][128 * 20];
    __shared__ float2 sRow[2][128];      // [wn][row] partial (sum, sumsq)
    __shared__ float s_bias[128], s_g[128], s_b[128];

    const int tid = threadIdx.x;
    const int wid = tid >> 5, lane = tid & 31;
    const int grp = lane >> 2, tig = lane & 3;
    const int wm = wid & 3, wn = wid >> 2;
    const int tileM = blockIdx.x * 128;
    const int rBase = wm * 32;           // warp row base
    const int cBase = wn * 64;           // warp col base

    if (tid < 128) { s_bias[tid] = bias[tid]; s_g[tid] = gamma[tid]; s_b[tid] = beta[tid]; }

    float c[2][8][4];
#pragma unroll
    for (int mi = 0; mi < 2; mi++)
#pragma unroll
        for (int ni = 0; ni < 8; ni++)
#pragma unroll
            for (int j = 0; j < 4; j++) c[mi][ni][j] = 0.f;

    // prefetch helper (inlined twice)
#define PREFETCH(CH, BUF)                                                      \
    {                                                                          \
        int k0_ = (CH) * 16;                                                   \
        _Pragma("unroll")                                                      \
        for (int it = 0; it < 2; it++) {                                       \
            int id = tid + it * 256;                                           \
            int m_ = id >> 2, pt_ = (id & 3) * 4;                              \
            cp16(smem_u32(&sA[BUF][m_ * 20 + pt_]),                            \
                 g_a + (size_t)(tileM + m_) * KT + k0_ + pt_);                 \
            cp16(smem_u32(&sB[BUF][m_ * 20 + pt_]),                            \
                 g_wt + (size_t)m_ * KT + k0_ + pt_);                          \
        }                                                                      \
        asm volatile("cp.async.commit_group;" ::: "memory");                   \
    }

    PREFETCH(0, 0);
    for (int ch = 0; ch < NCH; ch++) {
        const int buf = ch & 1;
        if (ch + 1 < NCH) {
            PREFETCH(ch + 1, (ch + 1) & 1);
            asm volatile("cp.async.wait_group 1;" ::: "memory");
        } else {
            asm volatile("cp.async.wait_group 0;" ::: "memory");
        }
        __syncthreads();

#pragma unroll
        for (int ks = 0; ks < 2; ks++) {
            const int kb = ks * 8 + tig;
            uint32_t a[2][4];
#pragma unroll
            for (int mi = 0; mi < 2; mi++) {
                const float* pa = &sA[buf][(rBase + mi * 16 + grp) * 20 + kb];
                a[mi][0] = __float_as_uint(pa[0]);
                a[mi][1] = __float_as_uint(pa[8 * 20]);
                a[mi][2] = __float_as_uint(pa[4]);
                a[mi][3] = __float_as_uint(pa[8 * 20 + 4]);
            }
            uint32_t b[8][2];
#pragma unroll
            for (int ni = 0; ni < 8; ni++) {
                const float* pb = &sB[buf][(cBase + ni * 8 + grp) * 20 + kb];
                b[ni][0] = __float_as_uint(pb[0]);
                b[ni][1] = __float_as_uint(pb[4]);
            }
#pragma unroll
            for (int mi = 0; mi < 2; mi++)
#pragma unroll
                for (int ni = 0; ni < 8; ni++)
                    mma_tf32(c[mi][ni], a[mi], b[ni]);
        }
        __syncthreads();
    }
#undef PREFETCH

    // ---- epilogue: bias, per-row LN stats, normalize, ReLU, store ----
#pragma unroll
    for (int ni = 0; ni < 8; ni++) {
        int col = cBase + ni * 8 + 2 * tig;
        float b0 = s_bias[col], b1 = s_bias[col + 1];
#pragma unroll
        for (int mi = 0; mi < 2; mi++) {
            c[mi][ni][0] += b0; c[mi][ni][1] += b1;
            c[mi][ni][2] += b0; c[mi][ni][3] += b1;
        }
    }
    // row sums over this warp's 64 cols: rows rBase+mi*16+h*8+grp
#pragma unroll
    for (int mi = 0; mi < 2; mi++)
#pragma unroll
        for (int h = 0; h < 2; h++) {
            float s = 0.f, ss = 0.f;
#pragma unroll
            for (int ni = 0; ni < 8; ni++) {
                float v0 = c[mi][ni][2 * h], v1 = c[mi][ni][2 * h + 1];
                s += v0 + v1;
                ss += v0 * v0 + v1 * v1;
            }
            s  += __shfl_xor_sync(0xffffffffu, s, 1);
            s  += __shfl_xor_sync(0xffffffffu, s, 2);
            ss += __shfl_xor_sync(0xffffffffu, ss, 1);
            ss += __shfl_xor_sync(0xffffffffu, ss, 2);
            if (tig == 0)
                sRow[wn][rBase + mi * 16 + h * 8 + grp] = make_float2(s, ss);
        }
    __syncthreads();

#pragma unroll
    for (int mi = 0; mi < 2; mi++)
#pragma unroll
        for (int h = 0; h < 2; h++) {
            int row = rBase + mi * 16 + h * 8 + grp;
            int gRow = tileM + row;
            if (gRow >= NN) continue;
            float2 p0 = sRow[0][row], p1 = sRow[1][row];
            float s = p0.x + p1.x, ss = p0.y + p1.y;
            float mean = s * (1.0f / DD);
            float var  = ss * (1.0f / DD) - mean * mean;
            float rstd = rsqrtf(var + LN_EPS);
#pragma unroll
            for (int ni = 0; ni < 8; ni++) {
                int col = cBase + ni * 8 + 2 * tig;
                float2 r;
                r.x = fmaxf((c[mi][ni][2 * h]     - mean) * rstd * s_g[col]     + s_b[col],     0.f);
                r.y = fmaxf((c[mi][ni][2 * h + 1] - mean) * rstd * s_g[col + 1] + s_b[col + 1], 0.f);
                *(float2*)(out + (size_t)gRow * DD + col) = r;
            }
        }
}

// ---------------------------------------------------------------------------
extern "C" void kernel_launch(void* const* d_in, const int* in_sizes, int n_in,
                              void* d_out, int out_size) {
    const float* x  = (const float*)d_in[0];
    const void*  ei = d_in[1];
    const void*  et = d_in[2];
    int base = 3;
    if (n_in > 3 && in_sizes[3] == 1) base = 4;
    const float* Wrel  = (const float*)d_in[base + 0];
    const float* Wroot = (const float*)d_in[base + 1];
    const float* bias  = (const float*)d_in[base + 2];
    const float* gamma = (const float*)d_in[base + 3];
    const float* beta  = (const float*)d_in[base + 4];
    float* out = (float*)d_out;

    k_detect  <<<1, 256>>>((const unsigned int*)ei, (const unsigned int*)et);
    k_zero_cnt<<<(NR + 255) / 256, 256>>>();
    k_prep    <<<(EE + 255) / 256, 256>>>(ei, et);
    k_offsets <<<(NR + 255) / 256, 256>>>();
    k_bucket  <<<(EE + 255) / 256, 256>>>();
    k_gather  <<<(NR * 32 + 255) / 256, 256>>>(x);
    k_xcopy   <<<(NN * 32 + 255) / 256, 256>>>(x);
    k_wprep   <<<(128 * KT + 255) / 256, 256>>>(Wrel, Wroot);
    k_mma_ln  <<<NPAD / 128, 256>>>(bias, gamma, beta, out);
}

// round 6
// speedup vs baseline: 2.9496x; 1.0138x over previous
#include <cuda_runtime.h>
#include <cuda_bf16.h>
#include <cstdint>

// Problem constants
#define NN  50000
#define EE  1600000
#define DD  128
#define RR  8
#define NR  (NN*RR)      // 400000
#define KT  1152         // R*D + D
#define NPAD 50048       // 391 * 128
#define LN_EPS 1e-5f
#define NCH 72           // KT / 16

// Scratch (device globals — allocation is forbidden). .bss zero-init.
__device__ __align__(256) float g_a[(size_t)NPAD * KT];   // 230.6 MB: [node, 1152] tf32
__device__ __align__(256) float g_wt[128 * KT];           // weights^T [N=128, K=1152]
__device__ int g_cnt[NR], g_off[NR], g_cur[NR];
__device__ int g_src[EE], g_key[EE], g_srt[EE];
__device__ int g_total, g_ei64, g_et64;

// ---------------------------------------------------------------------------
static __device__ __forceinline__ float to_tf32(float f) {
    float r; asm("cvt.rna.tf32.f32 %0, %1;" : "=f"(r) : "f"(f)); return r;
}
static __device__ __forceinline__ uint32_t smem_u32(const void* p) {
    uint32_t a;
    asm("{ .reg .u64 t; cvta.to.shared.u64 t, %1; cvt.u32.u64 %0, t; }"
        : "=r"(a) : "l"(p));
    return a;
}
static __device__ __forceinline__ void cp16(uint32_t dst, const void* src) {
    asm volatile("cp.async.cg.shared.global [%0], [%1], 16;"
                 :: "r"(dst), "l"(src) : "memory");
}
static __device__ __forceinline__ void st_cs(float* p, float4 v) {
    asm volatile("st.global.cs.v4.f32 [%0], {%1,%2,%3,%4};"
                 :: "l"(p), "f"(v.x), "f"(v.y), "f"(v.z), "f"(v.w) : "memory");
}
static __device__ __forceinline__ void mma_tf32(float c[4], const uint32_t a[4],
                                                const uint32_t b[2]) {
    asm volatile(
        "mma.sync.aligned.m16n8k8.row.col.f32.tf32.tf32.f32 "
        "{%0,%1,%2,%3}, {%4,%5,%6,%7}, {%8,%9}, {%0,%1,%2,%3};"
        : "+f"(c[0]), "+f"(c[1]), "+f"(c[2]), "+f"(c[3])
        : "r"(a[0]), "r"(a[1]), "r"(a[2]), "r"(a[3]), "r"(b[0]), "r"(b[1]));
}

// ---------------------------------------------------------------------------
// dtype detection for index inputs (int64 vs int32)
// ---------------------------------------------------------------------------
__global__ void k_detect(const unsigned int* __restrict__ ei_w,
                         const unsigned int* __restrict__ et_w) {
    __shared__ unsigned int a_ei, a_et;
    if (threadIdx.x == 0) { a_ei = 0u; a_et = 0u; }
    __syncthreads();
    unsigned int vei = 0u, vet = 0u;
#pragma unroll
    for (int j = 0; j < 8; j++) {
        int idx = threadIdx.x * 8 + j;
        vei |= ei_w[2 * idx + 1];
        vet |= et_w[2 * idx + 1];
    }
    atomicOr(&a_ei, vei);
    atomicOr(&a_et, vet);
    __syncthreads();
    if (threadIdx.x == 0) {
        g_ei64 = (a_ei == 0u) ? 1 : 0;
        g_et64 = (a_et == 0u) ? 1 : 0;
    }
}

__global__ void k_zero_cnt() {
    int i = blockIdx.x * blockDim.x + threadIdx.x;
    if (i < NR) g_cnt[i] = 0;
    if (i == 0) g_total = 0;
}

__global__ void k_prep(const void* __restrict__ ei_v,
                       const void* __restrict__ et_v) {
    int e = blockIdx.x * blockDim.x + threadIdx.x;
    if (e >= EE) return;
    int s, d, r;
    if (g_ei64) {
        const long long* p = (const long long*)ei_v;
        s = (int)p[e];
        d = (int)p[EE + e];
    } else {
        const int* p = (const int*)ei_v;
        s = p[e];
        d = p[EE + e];
    }
    if (g_et64) r = (int)((const long long*)et_v)[e];
    else        r = ((const int*)et_v)[e];
    int key = d * RR + r;
    g_src[e] = s;
    g_key[e] = key;
    atomicAdd(&g_cnt[key], 1);
}

__global__ void k_offsets() {
    int i = blockIdx.x * blockDim.x + threadIdx.x;
    int lane = threadIdx.x & 31;
    int val = (i < NR) ? g_cnt[i] : 0;
    int incl = val;
#pragma unroll
    for (int o = 1; o < 32; o <<= 1) {
        int n = __shfl_up_sync(0xffffffffu, incl, o);
        if (lane >= o) incl += n;
    }
    int excl = incl - val;
    int wtot = __shfl_sync(0xffffffffu, incl, 31);
    int base = 0;
    if (lane == 0) base = atomicAdd(&g_total, wtot);
    base = __shfl_sync(0xffffffffu, base, 0);
    if (i < NR) {
        g_off[i] = base + excl;
        g_cur[i] = base + excl;
    }
}

__global__ void k_bucket() {
    int e = blockIdx.x * blockDim.x + threadIdx.x;
    if (e < EE) {
        int pos = atomicAdd(&g_cur[g_key[e]], 1);
        g_srt[pos] = g_src[e];
    }
}

// One warp per (dst,rel) bucket: g_a[node, rel*128..] = tf32(mean of x[src])
__global__ __launch_bounds__(256)
void k_gather(const float* __restrict__ x) {
    int w = (blockIdx.x * blockDim.x + threadIdx.x) >> 5;
    if (w >= NR) return;
    int lane = threadIdx.x & 31;
    int start = g_off[w];
    int n = g_cnt[w];
    float4 acc = make_float4(0.f, 0.f, 0.f, 0.f);
    int j = 0;
    for (; j + 3 < n; j += 4) {
        int s0 = g_srt[start + j];
        int s1 = g_srt[start + j + 1];
        int s2 = g_srt[start + j + 2];
        int s3 = g_srt[start + j + 3];
        float4 v0 = *(const float4*)(x + (size_t)s0 * DD + lane * 4);
        float4 v1 = *(const float4*)(x + (size_t)s1 * DD + lane * 4);
        float4 v2 = *(const float4*)(x + (size_t)s2 * DD + lane * 4);
        float4 v3 = *(const float4*)(x + (size_t)s3 * DD + lane * 4);
        acc.x += (v0.x + v1.x) + (v2.x + v3.x);
        acc.y += (v0.y + v1.y) + (v2.y + v3.y);
        acc.z += (v0.z + v1.z) + (v2.z + v3.z);
        acc.w += (v0.w + v1.w) + (v2.w + v3.w);
    }
    for (; j < n; j++) {
        int s0 = g_srt[start + j];
        float4 v0 = *(const float4*)(x + (size_t)s0 * DD + lane * 4);
        acc.x += v0.x; acc.y += v0.y; acc.z += v0.z; acc.w += v0.w;
    }
    float sc = 1.0f / fmaxf((float)n, 1.0f);
    int node = w >> 3, rel = w & 7;
    float4 o;
    o.x = to_tf32(acc.x * sc); o.y = to_tf32(acc.y * sc);
    o.z = to_tf32(acc.z * sc); o.w = to_tf32(acc.w * sc);
    st_cs(g_a + (size_t)node * KT + rel * 128 + lane * 4, o);
}

__global__ void k_xcopy(const float* __restrict__ x) {
    int i = blockIdx.x * blockDim.x + threadIdx.x;
    if (i >= NN * 32) return;
    int node = i >> 5, c = (i & 31) * 4;
    float4 v = *(const float4*)(x + (size_t)node * DD + c);
    float4 o;
    o.x = to_tf32(v.x); o.y = to_tf32(v.y);
    o.z = to_tf32(v.z); o.w = to_tf32(v.w);
    st_cs(g_a + (size_t)node * KT + 1024 + c, o);
}

__global__ void k_wprep(const float* __restrict__ Wrel,
                        const float* __restrict__ Wroot) {
    int i = blockIdx.x * blockDim.x + threadIdx.x;
    if (i >= 128 * KT) return;
    int n = i & 127, k = i >> 7;
    float v = (k < 1024) ? Wrel[(size_t)k * 128 + n]
                         : Wroot[(size_t)(k - 1024) * 128 + n];
    g_wt[(size_t)n * KT + k] = to_tf32(v);
}

// ---------------------------------------------------------------------------
// tf32 mma.sync GEMM (M=128/CTA, N=128, K=1152) + bias + LN + ReLU.
// 8 warps in 4x2; warp tile 32x64 via m16n8k8. 4-stage cp.async pipeline,
// BK=16, ONE __syncthreads per chunk. Smem tiles [row][20] (pad 4).
// ---------------------------------------------------------------------------
__global__ void __launch_bounds__(256, 2)
k_mma_ln(const float* __restrict__ bias, const float* __restrict__ gamma,
         const float* __restrict__ beta, float* __restrict__ out) {
    __shared__ float sA[4][128 * 20];
    __shared__ float sB[4][128 * 20];
    __shared__ float2 sRow[2][128];      // [wn][row] partial (sum, sumsq)
    __shared__ float s_bias[128], s_g[128], s_b[128];

    const int tid = threadIdx.x;
    const int wid = tid >> 5, lane = tid & 31;
    const int grp = lane >> 2, tig = lane & 3;
    const int wm = wid & 3, wn = wid >> 2;
    const int tileM = blockIdx.x * 128;
    const int rBase = wm * 32;           // warp row base
    const int cBase = wn * 64;           // warp col base

    if (tid < 128) { s_bias[tid] = bias[tid]; s_g[tid] = gamma[tid]; s_b[tid] = beta[tid]; }

    float c[2][8][4];
#pragma unroll
    for (int mi = 0; mi < 2; mi++)
#pragma unroll
        for (int ni = 0; ni < 8; ni++)
#pragma unroll
            for (int j = 0; j < 4; j++) c[mi][ni][j] = 0.f;

    // per-thread fixed source/dest for prefetch: 2 (row, unit) pairs
    const int m0 = tid >> 2, p0 = (tid & 3) * 4;
    const int m1 = (tid + 256) >> 2, p1 = ((tid + 256) & 3) * 4;

#define PREFETCH(CH)                                                           \
    {                                                                          \
        int ch_ = (CH);                                                        \
        if (ch_ < NCH) {                                                       \
            int buf_ = ch_ & 3;                                                \
            int k0_ = ch_ * 16;                                                \
            cp16(smem_u32(&sA[buf_][m0 * 20 + p0]),                            \
                 g_a + (size_t)(tileM + m0) * KT + k0_ + p0);                  \
            cp16(smem_u32(&sB[buf_][m0 * 20 + p0]),                            \
                 g_wt + (size_t)m0 * KT + k0_ + p0);                           \
            cp16(smem_u32(&sA[buf_][m1 * 20 + p1]),                            \
                 g_a + (size_t)(tileM + m1) * KT + k0_ + p1);                  \
            cp16(smem_u32(&sB[buf_][m1 * 20 + p1]),                            \
                 g_wt + (size_t)m1 * KT + k0_ + p1);                           \
        }                                                                      \
        asm volatile("cp.async.commit_group;" ::: "memory");                   \
    }

    PREFETCH(0); PREFETCH(1); PREFETCH(2);

    for (int ch = 0; ch < NCH; ch++) {
        const int buf = ch & 3;
        asm volatile("cp.async.wait_group 2;" ::: "memory");
        __syncthreads();
        PREFETCH(ch + 3);   // writes buf (ch-1)&3 — safe: all warps passed sync

#pragma unroll
        for (int ks = 0; ks < 2; ks++) {
            const int kb = ks * 8 + tig;
            uint32_t a[2][4];
#pragma unroll
            for (int mi = 0; mi < 2; mi++) {
                const float* pa = &sA[buf][(rBase + mi * 16 + grp) * 20 + kb];
                a[mi][0] = __float_as_uint(pa[0]);
                a[mi][1] = __float_as_uint(pa[8 * 20]);
                a[mi][2] = __float_as_uint(pa[4]);
                a[mi][3] = __float_as_uint(pa[8 * 20 + 4]);
            }
            uint32_t b[8][2];
#pragma unroll
            for (int ni = 0; ni < 8; ni++) {
                const float* pb = &sB[buf][(cBase + ni * 8 + grp) * 20 + kb];
                b[ni][0] = __float_as_uint(pb[0]);
                b[ni][1] = __float_as_uint(pb[4]);
            }
#pragma unroll
            for (int mi = 0; mi < 2; mi++)
#pragma unroll
                for (int ni = 0; ni < 8; ni++)
                    mma_tf32(c[mi][ni], a[mi], b[ni]);
        }
    }
#undef PREFETCH
    __syncthreads();   // last buffers no longer needed; reuse smem region safely

    // ---- epilogue: bias, per-row LN stats, normalize, ReLU, store ----
#pragma unroll
    for (int ni = 0; ni < 8; ni++) {
        int col = cBase + ni * 8 + 2 * tig;
        float b0 = s_bias[col], b1 = s_bias[col + 1];
#pragma unroll
        for (int mi = 0; mi < 2; mi++) {
            c[mi][ni][0] += b0; c[mi][ni][1] += b1;
            c[mi][ni][2] += b0; c[mi][ni][3] += b1;
        }
    }
#pragma unroll
    for (int mi = 0; mi < 2; mi++)
#pragma unroll
        for (int h = 0; h < 2; h++) {
            float s = 0.f, ss = 0.f;
#pragma unroll
            for (int ni = 0; ni < 8; ni++) {
                float v0 = c[mi][ni][2 * h], v1 = c[mi][ni][2 * h + 1];
                s += v0 + v1;
                ss += v0 * v0 + v1 * v1;
            }
            s  += __shfl_xor_sync(0xffffffffu, s, 1);
            s  += __shfl_xor_sync(0xffffffffu, s, 2);
            ss += __shfl_xor_sync(0xffffffffu, ss, 1);
            ss += __shfl_xor_sync(0xffffffffu, ss, 2);
            if (tig == 0)
                sRow[wn][rBase + mi * 16 + h * 8 + grp] = make_float2(s, ss);
        }
    __syncthreads();

#pragma unroll
    for (int mi = 0; mi < 2; mi++)
#pragma unroll
        for (int h = 0; h < 2; h++) {
            int row = rBase + mi * 16 + h * 8 + grp;
            int gRow = tileM + row;
            if (gRow >= NN) continue;
            float2 p0 = sRow[0][row], p1 = sRow[1][row];
            float s = p0.x + p1.x, ss = p0.y + p1.y;
            float mean = s * (1.0f / DD);
            float var  = ss * (1.0f / DD) - mean * mean;
            float rstd = rsqrtf(var + LN_EPS);
#pragma unroll
            for (int ni = 0; ni < 8; ni++) {
                int col = cBase + ni * 8 + 2 * tig;
                float2 r;
                r.x = fmaxf((c[mi][ni][2 * h]     - mean) * rstd * s_g[col]     + s_b[col],     0.f);
                r.y = fmaxf((c[mi][ni][2 * h + 1] - mean) * rstd * s_g[col + 1] + s_b[col + 1], 0.f);
                *(float2*)(out + (size_t)gRow * DD + col) = r;
            }
        }
}

// ---------------------------------------------------------------------------
extern "C" void kernel_launch(void* const* d_in, const int* in_sizes, int n_in,
                              void* d_out, int out_size) {
    const float* x  = (const float*)d_in[0];
    const void*  ei = d_in[1];
    const void*  et = d_in[2];
    int base = 3;
    if (n_in > 3 && in_sizes[3] == 1) base = 4;
    const float* Wrel  = (const float*)d_in[base + 0];
    const float* Wroot = (const float*)d_in[base + 1];
    const float* bias  = (const float*)d_in[base + 2];
    const float* gamma = (const float*)d_in[base + 3];
    const float* beta  = (const float*)d_in[base + 4];
    float* out = (float*)d_out;

    k_detect  <<<1, 256>>>((const unsigned int*)ei, (const unsigned int*)et);
    k_zero_cnt<<<(NR + 255) / 256, 256>>>();
    k_prep    <<<(EE + 255) / 256, 256>>>(ei, et);
    k_offsets <<<(NR + 255) / 256, 256>>>();
    k_bucket  <<<(EE + 255) / 256, 256>>>();
    k_gather  <<<(NR * 32 + 255) / 256, 256>>>(x);
    k_xcopy   <<<(NN * 32 + 255) / 256, 256>>>(x);
    k_wprep   <<<(128 * KT + 255) / 256, 256>>>(Wrel, Wroot);
    k_mma_ln  <<<NPAD / 128, 256>>>(bias, gamma, beta, out);
}

// round 7
// speedup vs baseline: 3.9585x; 1.3421x over previous
#include <cuda_runtime.h>
#include <cuda_fp16.h>
#include <cstdint>

// Problem constants
#define NN  50000
#define EE  1600000
#define DD  128
#define RR  8
#define NR  (NN*RR)      // 400000
#define KT  1152         // R*D + D
#define NPAD 50048       // 391 * 128
#define LN_EPS 1e-5f
#define NCH 72           // KT / 16

// Scratch (device globals — allocation is forbidden). .bss zero-init.
__device__ __align__(256) unsigned short g_a[(size_t)NPAD * KT]; // 115 MB fp16 A
__device__ __align__(256) unsigned short g_wt[128 * KT];         // fp16 W^T [N=128,K]
__device__ __align__(256) unsigned short g_x16[NN * DD];         // fp16 copy of x
__device__ int g_cnt[NR], g_off[NR], g_cur[NR];
__device__ int g_src[EE], g_key[EE], g_srt[EE];
__device__ int g_total, g_ei64, g_et64;

// ---------------------------------------------------------------------------
static __device__ __forceinline__ uint32_t smem_u32(const void* p) {
    uint32_t a;
    asm("{ .reg .u64 t; cvta.to.shared.u64 t, %1; cvt.u32.u64 %0, t; }"
        : "=r"(a) : "l"(p));
    return a;
}
static __device__ __forceinline__ void cp16(uint32_t dst, const void* src) {
    asm volatile("cp.async.cg.shared.global [%0], [%1], 16;"
                 :: "r"(dst), "l"(src) : "memory");
}
static __device__ __forceinline__ void st_cs_u2(void* p, uint32_t a, uint32_t b) {
    asm volatile("st.global.cs.v2.u32 [%0], {%1,%2};"
                 :: "l"(p), "r"(a), "r"(b) : "memory");
}
static __device__ __forceinline__ uint32_t h2u(__half2 h) {
    return *(uint32_t*)&h;
}
static __device__ __forceinline__ void mma_f16(float c[4], const uint32_t a[4],
                                               const uint32_t b[2]) {
    asm volatile(
        "mma.sync.aligned.m16n8k16.row.col.f32.f16.f16.f32 "
        "{%0,%1,%2,%3}, {%4,%5,%6,%7}, {%8,%9}, {%0,%1,%2,%3};"
        : "+f"(c[0]), "+f"(c[1]), "+f"(c[2]), "+f"(c[3])
        : "r"(a[0]), "r"(a[1]), "r"(a[2]), "r"(a[3]), "r"(b[0]), "r"(b[1]));
}

// ---------------------------------------------------------------------------
// dtype detection for index inputs (int64 vs int32)
// ---------------------------------------------------------------------------
__global__ void k_detect(const unsigned int* __restrict__ ei_w,
                         const unsigned int* __restrict__ et_w) {
    __shared__ unsigned int a_ei, a_et;
    if (threadIdx.x == 0) { a_ei = 0u; a_et = 0u; }
    __syncthreads();
    unsigned int vei = 0u, vet = 0u;
#pragma unroll
    for (int j = 0; j < 8; j++) {
        int idx = threadIdx.x * 8 + j;
        vei |= ei_w[2 * idx + 1];
        vet |= et_w[2 * idx + 1];
    }
    atomicOr(&a_ei, vei);
    atomicOr(&a_et, vet);
    __syncthreads();
    if (threadIdx.x == 0) {
        g_ei64 = (a_ei == 0u) ? 1 : 0;
        g_et64 = (a_et == 0u) ? 1 : 0;
    }
}

__global__ void k_zero_cnt() {
    int i = blockIdx.x * blockDim.x + threadIdx.x;
    if (i < NR) g_cnt[i] = 0;
    if (i == 0) g_total = 0;
}

__global__ void k_prep(const void* __restrict__ ei_v,
                       const void* __restrict__ et_v) {
    int e = blockIdx.x * blockDim.x + threadIdx.x;
    if (e >= EE) return;
    int s, d, r;
    if (g_ei64) {
        const long long* p = (const long long*)ei_v;
        s = (int)p[e];
        d = (int)p[EE + e];
    } else {
        const int* p = (const int*)ei_v;
        s = p[e];
        d = p[EE + e];
    }
    if (g_et64) r = (int)((const long long*)et_v)[e];
    else        r = ((const int*)et_v)[e];
    int key = d * RR + r;
    g_src[e] = s;
    g_key[e] = key;
    atomicAdd(&g_cnt[key], 1);
}

__global__ void k_offsets() {
    int i = blockIdx.x * blockDim.x + threadIdx.x;
    int lane = threadIdx.x & 31;
    int val = (i < NR) ? g_cnt[i] : 0;
    int incl = val;
#pragma unroll
    for (int o = 1; o < 32; o <<= 1) {
        int n = __shfl_up_sync(0xffffffffu, incl, o);
        if (lane >= o) incl += n;
    }
    int excl = incl - val;
    int wtot = __shfl_sync(0xffffffffu, incl, 31);
    int base = 0;
    if (lane == 0) base = atomicAdd(&g_total, wtot);
    base = __shfl_sync(0xffffffffu, base, 0);
    if (i < NR) {
        g_off[i] = base + excl;
        g_cur[i] = base + excl;
    }
}

__global__ void k_bucket() {
    int e = blockIdx.x * blockDim.x + threadIdx.x;
    if (e < EE) {
        int pos = atomicAdd(&g_cur[g_key[e]], 1);
        g_srt[pos] = g_src[e];
    }
}

// fp16 copy of x + root slice of A (cols 1024..1151)
__global__ void k_xprep(const float* __restrict__ x) {
    int i = blockIdx.x * blockDim.x + threadIdx.x;
    if (i >= NN * 32) return;
    int node = i >> 5, c = (i & 31) * 4;
    float4 v = *(const float4*)(x + (size_t)node * DD + c);
    uint32_t u0 = h2u(__floats2half2_rn(v.x, v.y));
    uint32_t u1 = h2u(__floats2half2_rn(v.z, v.w));
    ((uint2*)g_x16)[i] = make_uint2(u0, u1);
    st_cs_u2(g_a + (size_t)node * KT + 1024 + c, u0, u1);
}

// One warp per (dst,rel) bucket: A[node, rel*128..] = fp16(mean of x16[src])
__global__ __launch_bounds__(256)
void k_gather() {
    int w = (blockIdx.x * blockDim.x + threadIdx.x) >> 5;
    if (w >= NR) return;
    int lane = threadIdx.x & 31;
    int start = g_off[w];
    int n = g_cnt[w];
    const uint2* xv = (const uint2*)g_x16;   // 4 halves per entry, 32 per row
    float4 acc = make_float4(0.f, 0.f, 0.f, 0.f);
    int j = 0;
    for (; j + 3 < n; j += 4) {
        int s0 = g_srt[start + j];
        int s1 = g_srt[start + j + 1];
        int s2 = g_srt[start + j + 2];
        int s3 = g_srt[start + j + 3];
        uint2 u0 = xv[s0 * 32 + lane];
        uint2 u1 = xv[s1 * 32 + lane];
        uint2 u2 = xv[s2 * 32 + lane];
        uint2 u3 = xv[s3 * 32 + lane];
        float2 a0 = __half22float2(*(__half2*)&u0.x), b0 = __half22float2(*(__half2*)&u0.y);
        float2 a1 = __half22float2(*(__half2*)&u1.x), b1 = __half22float2(*(__half2*)&u1.y);
        float2 a2 = __half22float2(*(__half2*)&u2.x), b2 = __half22float2(*(__half2*)&u2.y);
        float2 a3 = __half22float2(*(__half2*)&u3.x), b3 = __half22float2(*(__half2*)&u3.y);
        acc.x += (a0.x + a1.x) + (a2.x + a3.x);
        acc.y += (a0.y + a1.y) + (a2.y + a3.y);
        acc.z += (b0.x + b1.x) + (b2.x + b3.x);
        acc.w += (b0.y + b1.y) + (b2.y + b3.y);
    }
    for (; j < n; j++) {
        int s0 = g_srt[start + j];
        uint2 u0 = xv[s0 * 32 + lane];
        float2 a0 = __half22float2(*(__half2*)&u0.x), b0 = __half22float2(*(__half2*)&u0.y);
        acc.x += a0.x; acc.y += a0.y; acc.z += b0.x; acc.w += b0.y;
    }
    float sc = 1.0f / fmaxf((float)n, 1.0f);
    uint32_t u0 = h2u(__floats2half2_rn(acc.x * sc, acc.y * sc));
    uint32_t u1 = h2u(__floats2half2_rn(acc.z * sc, acc.w * sc));
    int node = w >> 3, rel = w & 7;
    st_cs_u2(g_a + (size_t)node * KT + rel * 128 + lane * 4, u0, u1);
}

// weights transposed fp16: g_wt[n, k] = fp16(W[k, n])
__global__ void k_wprep(const float* __restrict__ Wrel,
                        const float* __restrict__ Wroot) {
    int i = blockIdx.x * blockDim.x + threadIdx.x;
    if (i >= 128 * KT) return;
    int n = i & 127, k = i >> 7;
    float v = (k < 1024) ? Wrel[(size_t)k * 128 + n]
                         : Wroot[(size_t)(k - 1024) * 128 + n];
    g_wt[(size_t)n * KT + k] = __half_as_ushort(__float2half_rn(v));
}

// ---------------------------------------------------------------------------
// fp16 mma.sync GEMM (M=128/CTA, N=128, K=1152) + bias + LN + ReLU.
// 8 warps in 4x2; warp tile 32x64 via m16n8k16 (BK=16, fp32 accum).
// 4-stage cp.async pipeline, one __syncthreads per chunk.
// Smem tiles: halves, row stride 24 (pad 8) -> conflict-free frag LDS.
// ---------------------------------------------------------------------------
__global__ void __launch_bounds__(256, 2)
k_mma_ln(const float* __restrict__ bias, const float* __restrict__ gamma,
         const float* __restrict__ beta, float* __restrict__ out) {
    __shared__ unsigned short sA[4][128 * 24];
    __shared__ unsigned short sB[4][128 * 24];
    __shared__ float2 sRow[2][128];
    __shared__ float s_bias[128], s_g[128], s_b[128];

    const int tid = threadIdx.x;
    const int wid = tid >> 5, lane = tid & 31;
    const int grp = lane >> 2, tig = lane & 3;
    const int wm = wid & 3, wn = wid >> 2;
    const int tileM = blockIdx.x * 128;
    const int rBase = wm * 32;
    const int cBase = wn * 64;

    if (tid < 128) { s_bias[tid] = bias[tid]; s_g[tid] = gamma[tid]; s_b[tid] = beta[tid]; }

    float c[2][8][4];
#pragma unroll
    for (int mi = 0; mi < 2; mi++)
#pragma unroll
        for (int ni = 0; ni < 8; ni++)
#pragma unroll
            for (int j = 0; j < 4; j++) c[mi][ni][j] = 0.f;

    // per-thread fixed (row, 8-half chunk) for prefetch
    const int m0 = tid >> 1, p0 = (tid & 1) * 8;

#define PREFETCH(CH)                                                           \
    {                                                                          \
        int ch_ = (CH);                                                        \
        if (ch_ < NCH) {                                                       \
            int buf_ = ch_ & 3;                                                \
            int k0_ = ch_ * 16;                                                \
            cp16(smem_u32(&sA[buf_][m0 * 24 + p0]),                            \
                 g_a + (size_t)(tileM + m0) * KT + k0_ + p0);                  \
            cp16(smem_u32(&sB[buf_][m0 * 24 + p0]),                            \
                 g_wt + (size_t)m0 * KT + k0_ + p0);                           \
        }                                                                      \
        asm volatile("cp.async.commit_group;" ::: "memory");                   \
    }

    PREFETCH(0); PREFETCH(1); PREFETCH(2);

    for (int ch = 0; ch < NCH; ch++) {
        const int buf = ch & 3;
        asm volatile("cp.async.wait_group 2;" ::: "memory");
        __syncthreads();
        PREFETCH(ch + 3);

        uint32_t a[2][4];
#pragma unroll
        for (int mi = 0; mi < 2; mi++) {
            const unsigned short* pa = &sA[buf][(rBase + mi * 16 + grp) * 24 + tig * 2];
            a[mi][0] = *(const uint32_t*)pa;
            a[mi][1] = *(const uint32_t*)(pa + 8 * 24);
            a[mi][2] = *(const uint32_t*)(pa + 8);
            a[mi][3] = *(const uint32_t*)(pa + 8 * 24 + 8);
        }
        uint32_t b[8][2];
#pragma unroll
        for (int ni = 0; ni < 8; ni++) {
            const unsigned short* pb = &sB[buf][(cBase + ni * 8 + grp) * 24 + tig * 2];
            b[ni][0] = *(const uint32_t*)pb;
            b[ni][1] = *(const uint32_t*)(pb + 8);
        }
#pragma unroll
        for (int mi = 0; mi < 2; mi++)
#pragma unroll
            for (int ni = 0; ni < 8; ni++)
                mma_f16(c[mi][ni], a[mi], b[ni]);
    }
#undef PREFETCH
    __syncthreads();

    // ---- epilogue: bias, per-row LN stats, normalize, ReLU, store ----
#pragma unroll
    for (int ni = 0; ni < 8; ni++) {
        int col = cBase + ni * 8 + 2 * tig;
        float b0 = s_bias[col], b1 = s_bias[col + 1];
#pragma unroll
        for (int mi = 0; mi < 2; mi++) {
            c[mi][ni][0] += b0; c[mi][ni][1] += b1;
            c[mi][ni][2] += b0; c[mi][ni][3] += b1;
        }
    }
#pragma unroll
    for (int mi = 0; mi < 2; mi++)
#pragma unroll
        for (int h = 0; h < 2; h++) {
            float s = 0.f, ss = 0.f;
#pragma unroll
            for (int ni = 0; ni < 8; ni++) {
                float v0 = c[mi][ni][2 * h], v1 = c[mi][ni][2 * h + 1];
                s += v0 + v1;
                ss += v0 * v0 + v1 * v1;
            }
            s  += __shfl_xor_sync(0xffffffffu, s, 1);
            s  += __shfl_xor_sync(0xffffffffu, s, 2);
            ss += __shfl_xor_sync(0xffffffffu, ss, 1);
            ss += __shfl_xor_sync(0xffffffffu, ss, 2);
            if (tig == 0)
                sRow[wn][rBase + mi * 16 + h * 8 + grp] = make_float2(s, ss);
        }
    __syncthreads();

#pragma unroll
    for (int mi = 0; mi < 2; mi++)
#pragma unroll
        for (int h = 0; h < 2; h++) {
            int row = rBase + mi * 16 + h * 8 + grp;
            int gRow = tileM + row;
            if (gRow >= NN) continue;
            float2 p0v = sRow[0][row], p1v = sRow[1][row];
            float s = p0v.x + p1v.x, ss = p0v.y + p1v.y;
            float mean = s * (1.0f / DD);
            float var  = ss * (1.0f / DD) - mean * mean;
            float rstd = rsqrtf(var + LN_EPS);
#pragma unroll
            for (int ni = 0; ni < 8; ni++) {
                int col = cBase + ni * 8 + 2 * tig;
                float2 r;
                r.x = fmaxf((c[mi][ni][2 * h]     - mean) * rstd * s_g[col]     + s_b[col],     0.f);
                r.y = fmaxf((c[mi][ni][2 * h + 1] - mean) * rstd * s_g[col + 1] + s_b[col + 1], 0.f);
                *(float2*)(out + (size_t)gRow * DD + col) = r;
            }
        }
}

// ---------------------------------------------------------------------------
extern "C" void kernel_launch(void* const* d_in, const int* in_sizes, int n_in,
                              void* d_out, int out_size) {
    const float* x  = (const float*)d_in[0];
    const void*  ei = d_in[1];
    const void*  et = d_in[2];
    int base = 3;
    if (n_in > 3 && in_sizes[3] == 1) base = 4;
    const float* Wrel  = (const float*)d_in[base + 0];
    const float* Wroot = (const float*)d_in[base + 1];
    const float* bias  = (const float*)d_in[base + 2];
    const float* gamma = (const float*)d_in[base + 3];
    const float* beta  = (const float*)d_in[base + 4];
    float* out = (float*)d_out;

    k_detect  <<<1, 256>>>((const unsigned int*)ei, (const unsigned int*)et);
    k_zero_cnt<<<(NR + 255) / 256, 256>>>();
    k_prep    <<<(EE + 255) / 256, 256>>>(ei, et);
    k_offsets <<<(NR + 255) / 256, 256>>>();
    k_bucket  <<<(EE + 255) / 256, 256>>>();
    k_xprep   <<<(NN * 32 + 255) / 256, 256>>>(x);
    k_gather  <<<(NR * 32 + 255) / 256, 256>>>();
    k_wprep   <<<(128 * KT + 255) / 256, 256>>>(Wrel, Wroot);
    k_mma_ln  <<<NPAD / 128, 256>>>(bias, gamma, beta, out);
}